// round 7
// baseline (speedup 1.0000x reference)
#include <cuda_runtime.h>
#include <math.h>

#define B_ 8
#define L_ 1024
#define D_ 256
#define U_ 256

typedef unsigned long long ull;

// ---------------- scratch (device globals; no allocation allowed) ----------
__device__ float g_EW[D_ * U_];          // E @ Wx            (256 KB)
__device__ float g_rnorm[B_ * L_];       // 1/max(rowsum,eps) (32 KB)
__device__ float g_t[B_ * L_ * U_];      // (seq@EW)*rnorm    (8 MB)
__device__ float g_xp0[B_ * L_ * U_];    // G^T @ t partials  (8 MB each)
__device__ float g_xp1[B_ * L_ * U_];
__device__ float g_xp2[B_ * L_ * U_];
__device__ float g_xp3[B_ * L_ * U_];

// ---------------- packed f32x2 helpers (sm_103a) ----------------------------
__device__ __forceinline__ ull pk2(float lo, float hi) {
    ull r; asm("mov.b64 %0,{%1,%2};" : "=l"(r) : "f"(lo), "f"(hi)); return r;
}
__device__ __forceinline__ void ffma2(ull& d, ull a, ull b) {
    asm("fma.rn.f32x2 %0,%1,%2,%0;" : "+l"(d) : "l"(a), "l"(b));
}
__device__ __forceinline__ float2 up2(ull a) {
    float lo, hi; asm("mov.b64 {%0,%1},%2;" : "=f"(lo), "=f"(hi) : "l"(a));
    float2 r; r.x = lo; r.y = hi; return r;
}
// tanh(z) = 1 - 2/(1+exp(2z)) via MUFU (rel err ~1e-6; validated R3-R6)
__device__ __forceinline__ float fast_tanh(float z) {
    float t2 = z * 2.885390081777927f;  // 2*log2(e)
    float ex; asm("ex2.approx.f32 %0,%1;" : "=f"(ex) : "f"(t2));
    float den = ex + 1.0f;
    float rc; asm("rcp.approx.f32 %0,%1;" : "=f"(rc) : "f"(den));
    return fmaf(-2.0f, rc, 1.0f);
}

// ---------------- 1) rnorm[b,l] = 1 / max(sum_m graph[b,l,m], 1e-7) ---------
__global__ __launch_bounds__(256) void norm_kernel(const float* __restrict__ graph,
                                                   float* __restrict__ rnorm) {
    int warp = (blockIdx.x * blockDim.x + threadIdx.x) >> 5;
    int lane = threadIdx.x & 31;
    if (warp >= B_ * L_) return;
    const float4* row = (const float4*)(graph + (size_t)warp * L_);
    float s = 0.f;
#pragma unroll
    for (int i = lane; i < L_ / 4; i += 32) {
        float4 v = row[i];
        s += (v.x + v.y) + (v.z + v.w);
    }
#pragma unroll
    for (int o = 16; o; o >>= 1) s += __shfl_xor_sync(0xffffffffu, s, o);
    if (lane == 0) rnorm[warp] = 1.f / fmaxf(s, 1e-7f);
}

// ---------------- 2) GEMM NN (proven R2 version): 128x128 tile, BK=16 -------
__global__ __launch_bounds__(256) void gemm_nn(const float* __restrict__ A,
                                               const float* __restrict__ Bm,
                                               float* __restrict__ C, int K,
                                               const float* __restrict__ rowscale) {
    __shared__ float As[2][16][128];
    __shared__ float Bs[2][16][128];
    const int N = 256;
    const int m0 = blockIdx.y * 128, n0 = blockIdx.x * 128;
    const int t = threadIdx.x;
    const int tx = t & 15, ty = t >> 4;

    ull acc[8][4];
#pragma unroll
    for (int i = 0; i < 8; i++)
#pragma unroll
        for (int j = 0; j < 4; j++) acc[i][j] = 0ull;

    int am[2], akg[2], bkk[2], bng[2];
#pragma unroll
    for (int i = 0; i < 2; i++) {
        int f4 = t + i * 256;
        am[i] = f4 >> 2; akg[i] = f4 & 3;
        bkk[i] = f4 >> 5; bng[i] = f4 & 31;
    }

    float4 ra[2], rb[2];
#pragma unroll
    for (int i = 0; i < 2; i++) {
        ra[i] = *(const float4*)(A + (size_t)(m0 + am[i]) * K + akg[i] * 4);
        rb[i] = *(const float4*)(Bm + (size_t)bkk[i] * N + n0 + bng[i] * 4);
    }

    int cur = 0;
    for (int k0 = 0; k0 < K; k0 += 16) {
#pragma unroll
        for (int i = 0; i < 2; i++) {
            As[cur][akg[i] * 4 + 0][am[i]] = ra[i].x;
            As[cur][akg[i] * 4 + 1][am[i]] = ra[i].y;
            As[cur][akg[i] * 4 + 2][am[i]] = ra[i].z;
            As[cur][akg[i] * 4 + 3][am[i]] = ra[i].w;
            *(float4*)&Bs[cur][bkk[i]][bng[i] * 4] = rb[i];
        }
        __syncthreads();
        if (k0 + 16 < K) {
#pragma unroll
            for (int i = 0; i < 2; i++) {
                ra[i] = *(const float4*)(A + (size_t)(m0 + am[i]) * K + k0 + 16 + akg[i] * 4);
                rb[i] = *(const float4*)(Bm + (size_t)(k0 + 16 + bkk[i]) * N + n0 + bng[i] * 4);
            }
        }
#pragma unroll
        for (int kk = 0; kk < 16; kk++) {
            float4 a0 = *(float4*)&As[cur][kk][ty * 8];
            float4 a1 = *(float4*)&As[cur][kk][ty * 8 + 4];
            float4 b0 = *(float4*)&Bs[cur][kk][tx * 8];
            float4 b1 = *(float4*)&Bs[cur][kk][tx * 8 + 4];
            ull bp0 = pk2(b0.x, b0.y), bp1 = pk2(b0.z, b0.w);
            ull bp2 = pk2(b1.x, b1.y), bp3 = pk2(b1.z, b1.w);
            float av[8] = {a0.x, a0.y, a0.z, a0.w, a1.x, a1.y, a1.z, a1.w};
#pragma unroll
            for (int i = 0; i < 8; i++) {
                ull ad = pk2(av[i], av[i]);
                ffma2(acc[i][0], ad, bp0);
                ffma2(acc[i][1], ad, bp1);
                ffma2(acc[i][2], ad, bp2);
                ffma2(acc[i][3], ad, bp3);
            }
        }
        cur ^= 1;
    }
#pragma unroll
    for (int i = 0; i < 8; i++) {
        int row = m0 + ty * 8 + i;
        float sc = rowscale ? rowscale[row] : 1.f;
        float2 v0 = up2(acc[i][0]), v1 = up2(acc[i][1]);
        float2 v2 = up2(acc[i][2]), v3 = up2(acc[i][3]);
        float4 o0 = make_float4(v0.x * sc, v0.y * sc, v1.x * sc, v1.y * sc);
        float4 o1 = make_float4(v2.x * sc, v2.y * sc, v3.x * sc, v3.y * sc);
        *(float4*)(C + (size_t)row * N + n0 + tx * 8) = o0;
        *(float4*)(C + (size_t)row * N + n0 + tx * 8 + 4) = o1;
    }
}

// ---------------- 3) GEMM TN, K-split 4: z = b*4 + ks, K quarter = 256 ------
__global__ __launch_bounds__(256) void gemm_tn(const float* __restrict__ A,
                                               const float* __restrict__ Bm,
                                               float* __restrict__ C0,
                                               float* __restrict__ C1,
                                               float* __restrict__ C2,
                                               float* __restrict__ C3) {
    __shared__ float As[2][16][128];
    __shared__ float Bs[2][16][128];
    const int N = 256, lda = L_;
    const int bz = blockIdx.z;
    const int b = bz >> 2, ks = bz & 3;
    const int kbeg = ks * (L_ / 4), kend = kbeg + (L_ / 4);
    const float* Ab = A + (size_t)b * L_ * L_;
    const float* Bb = Bm + (size_t)b * L_ * U_;
    float* Cs = (ks == 0) ? C0 : (ks == 1) ? C1 : (ks == 2) ? C2 : C3;
    float* C = Cs + (size_t)b * L_ * U_;
    const int m0 = blockIdx.y * 128, n0 = blockIdx.x * 128;
    const int t = threadIdx.x;
    const int tx = t & 15, ty = t >> 4;

    ull acc[8][4];
#pragma unroll
    for (int i = 0; i < 8; i++)
#pragma unroll
        for (int j = 0; j < 4; j++) acc[i][j] = 0ull;

    int kk_[2], g_[2];
#pragma unroll
    for (int i = 0; i < 2; i++) {
        int f4 = t + i * 256;
        kk_[i] = f4 >> 5; g_[i] = f4 & 31;
    }

    float4 ra[2], rb[2];
#pragma unroll
    for (int i = 0; i < 2; i++) {
        ra[i] = *(const float4*)(Ab + (size_t)(kbeg + kk_[i]) * lda + m0 + g_[i] * 4);
        rb[i] = *(const float4*)(Bb + (size_t)(kbeg + kk_[i]) * N + n0 + g_[i] * 4);
    }

    int cur = 0;
    for (int k0 = kbeg; k0 < kend; k0 += 16) {
#pragma unroll
        for (int i = 0; i < 2; i++) {
            *(float4*)&As[cur][kk_[i]][g_[i] * 4] = ra[i];
            *(float4*)&Bs[cur][kk_[i]][g_[i] * 4] = rb[i];
        }
        __syncthreads();
        if (k0 + 16 < kend) {
#pragma unroll
            for (int i = 0; i < 2; i++) {
                ra[i] = *(const float4*)(Ab + (size_t)(k0 + 16 + kk_[i]) * lda + m0 + g_[i] * 4);
                rb[i] = *(const float4*)(Bb + (size_t)(k0 + 16 + kk_[i]) * N + n0 + g_[i] * 4);
            }
        }
#pragma unroll
        for (int kk = 0; kk < 16; kk++) {
            float4 a0 = *(float4*)&As[cur][kk][ty * 8];
            float4 a1 = *(float4*)&As[cur][kk][ty * 8 + 4];
            float4 b0 = *(float4*)&Bs[cur][kk][tx * 8];
            float4 b1 = *(float4*)&Bs[cur][kk][tx * 8 + 4];
            ull bp0 = pk2(b0.x, b0.y), bp1 = pk2(b0.z, b0.w);
            ull bp2 = pk2(b1.x, b1.y), bp3 = pk2(b1.z, b1.w);
            float av[8] = {a0.x, a0.y, a0.z, a0.w, a1.x, a1.y, a1.z, a1.w};
#pragma unroll
            for (int i = 0; i < 8; i++) {
                ull ad = pk2(av[i], av[i]);
                ffma2(acc[i][0], ad, bp0);
                ffma2(acc[i][1], ad, bp1);
                ffma2(acc[i][2], ad, bp2);
                ffma2(acc[i][3], ad, bp3);
            }
        }
        cur ^= 1;
    }
#pragma unroll
    for (int i = 0; i < 8; i++) {
        int row = m0 + ty * 8 + i;
        float2 v0 = up2(acc[i][0]), v1 = up2(acc[i][1]);
        float2 v2 = up2(acc[i][2]), v3 = up2(acc[i][3]);
        float4 o0 = make_float4(v0.x, v0.y, v1.x, v1.y);
        float4 o1 = make_float4(v2.x, v2.y, v3.x, v3.y);
        *(float4*)(C + (size_t)row * N + n0 + tx * 8) = o0;
        *(float4*)(C + (size_t)row * N + n0 + tx * 8 + 4) = o1;
    }
}

// ---------------- 4) sequential scan --------------------------------------
// R2/R6 skeleton; SMEM weights repacked as ulonglong2 (LDS.128, 2 outputs per
// load) and the 3 SMEM-weight chunks interleaved into the RF loop so crossbar
// traffic overlaps the FMA stream.
#define RF_PAIRS 26
#define SM_PAIRS 6
#define WS2_ELEMS (SM_PAIRS * 2 * 256)                       // ulonglong2 count
#define SCAN_SMEM_BYTES (WS2_ELEMS * 16 + 4 * 256 * 4 + 2 * 256 * 4)

__global__ __launch_bounds__(256, 1) void scan_kernel(const float* __restrict__ Wh,
                                                      const float* __restrict__ xp0g,
                                                      const float* __restrict__ xp1g,
                                                      const float* __restrict__ xp2g,
                                                      const float* __restrict__ xp3g,
                                                      const float* __restrict__ bias,
                                                      float* __restrict__ out) {
    extern __shared__ unsigned char smraw[];
    ulonglong2* ws2 = (ulonglong2*)smraw;                    // 48 KB weights
    float* part = (float*)(smraw + WS2_ELEMS * 16);          // 4 KB partials
    float* hbuf = part + 4 * 256;                            // 2 KB h (double buf)

    const int tid = threadIdx.x;
    const int b = blockIdx.x;
    const int w = tid >> 5, l = tid & 31;
    const int ks = w >> 1, oh = w & 1;
    const int u0 = oh * 128 + l * 4;

    // ws2[(ps*2 + jp)*256 + tid] = { pair(k,k+1) for output u0+2jp,
    //                               pair(k,k+1) for output u0+2jp+1 },
    // k = ks*64 + 2*(RF_PAIRS + ps) for the owning thread's (ks,u0).
    for (int idx = tid; idx < WS2_ELEMS; idx += 256) {
        int e = idx >> 8;          // ps*2 + jp
        int r = idx & 255;         // owning thread id
        int ps = e >> 1, jp = e & 1;
        int wf = r >> 5, lf = r & 31;
        int ksf = wf >> 1, ohf = wf & 1;
        int uf = ohf * 128 + lf * 4 + 2 * jp;
        int kf = ksf * 64 + 2 * (RF_PAIRS + ps);
        ulonglong2 v;
        v.x = pk2(Wh[kf * U_ + uf], Wh[(kf + 1) * U_ + uf]);
        v.y = pk2(Wh[kf * U_ + uf + 1], Wh[(kf + 1) * U_ + uf + 1]);
        ws2[idx] = v;
    }

    ull wreg[4][RF_PAIRS];
#pragma unroll
    for (int j = 0; j < 4; j++)
#pragma unroll
        for (int p = 0; p < RF_PAIRS; p++) {
            int k = ks * 64 + 2 * p;
            wreg[j][p] = pk2(Wh[k * U_ + u0 + j], Wh[(k + 1) * U_ + u0 + j]);
        }

    hbuf[tid] = 0.f;
    hbuf[256 + tid] = 0.f;
    const float bv = bias[tid];
    __syncthreads();

    const float* xp0 = xp0g + (size_t)b * L_ * U_ + tid;
    const float* xp1 = xp1g + (size_t)b * L_ * U_ + tid;
    const float* xp2 = xp2g + (size_t)b * L_ * U_ + tid;
    const float* xp3 = xp3g + (size_t)b * L_ * U_ + tid;
    float* op = out + (size_t)b * L_ * U_ + tid;
    float xv = (xp0[0] + xp1[0]) + (xp2[0] + xp3[0]);
    int cur = 0;

    const ulonglong2* wp = ws2 + tid;   // element stride 256 per (ps*2+jp)

    for (int s = 0; s < L_; s++) {
        const ulonglong2* hp2 = (const ulonglong2*)(hbuf + cur * 256 + ks * 64);
        ull a0 = 0ull, a1 = 0ull, a2 = 0ull, a3 = 0ull;
#pragma unroll
        for (int q = 0; q < 13; q++) {   // RF pairs 0..25, SMEM chunks at q=4/8/12
            ulonglong2 hv = hp2[q];
            ffma2(a0, hv.x, wreg[0][2 * q]);
            ffma2(a1, hv.x, wreg[1][2 * q]);
            ffma2(a2, hv.x, wreg[2][2 * q]);
            ffma2(a3, hv.x, wreg[3][2 * q]);
            ffma2(a0, hv.y, wreg[0][2 * q + 1]);
            ffma2(a1, hv.y, wreg[1][2 * q + 1]);
            ffma2(a2, hv.y, wreg[2][2 * q + 1]);
            ffma2(a3, hv.y, wreg[3][2 * q + 1]);
            if (q == 4 || q == 8 || q == 12) {
                int qq = (q - 4) >> 2;           // 0,1,2
                ulonglong2 hvs = hp2[13 + qq];   // h pairs 26+2qq, 27+2qq
                int ps0 = 2 * qq, ps1 = 2 * qq + 1;
                ulonglong2 W0a = wp[(ps0 * 2 + 0) * 256];
                ulonglong2 W0b = wp[(ps0 * 2 + 1) * 256];
                ffma2(a0, hvs.x, W0a.x);
                ffma2(a1, hvs.x, W0a.y);
                ffma2(a2, hvs.x, W0b.x);
                ffma2(a3, hvs.x, W0b.y);
                ulonglong2 W1a = wp[(ps1 * 2 + 0) * 256];
                ulonglong2 W1b = wp[(ps1 * 2 + 1) * 256];
                ffma2(a0, hvs.y, W1a.x);
                ffma2(a1, hvs.y, W1a.y);
                ffma2(a2, hvs.y, W1b.x);
                ffma2(a3, hvs.y, W1b.y);
            }
        }
        float2 v0 = up2(a0), v1 = up2(a1), v2 = up2(a2), v3 = up2(a3);
        float4 pr = make_float4(v0.x + v0.y, v1.x + v1.y, v2.x + v2.y, v3.x + v3.y);
        *(float4*)&part[ks * 256 + u0] = pr;
        __syncthreads();

        float z = part[tid] + part[256 + tid] + part[512 + tid] + part[768 + tid]
                  + xv + bv;
        float h = fast_tanh(z);
        hbuf[(cur ^ 1) * 256 + tid] = h;
        op[(size_t)s * U_] = h;
        int sn = (s + 1 < L_) ? s + 1 : s;
        xv = (__ldg(xp0 + (size_t)sn * U_) + __ldg(xp1 + (size_t)sn * U_)) +
             (__ldg(xp2 + (size_t)sn * U_) + __ldg(xp3 + (size_t)sn * U_));
        cur ^= 1;
        __syncthreads();
    }
}

// ---------------- launch --------------------------------------------------
extern "C" void kernel_launch(void* const* d_in, const int* in_sizes, int n_in,
                              void* d_out, int out_size) {
    const float* seq = (const float*)d_in[0];    // (8,1024,256)
    const float* graph = (const float*)d_in[1];  // (8,1024,1024)
    const float* E = (const float*)d_in[2];      // (256,256)
    const float* Wx = (const float*)d_in[3];     // (256,256)
    const float* Wh = (const float*)d_in[4];     // (256,256)
    const float* bias = (const float*)d_in[5];   // (256,)
    float* out = (float*)d_out;                  // (8,1024,256)

    float *ew, *rn, *tt, *x0, *x1, *x2, *x3;
    cudaGetSymbolAddress((void**)&ew, g_EW);
    cudaGetSymbolAddress((void**)&rn, g_rnorm);
    cudaGetSymbolAddress((void**)&tt, g_t);
    cudaGetSymbolAddress((void**)&x0, g_xp0);
    cudaGetSymbolAddress((void**)&x1, g_xp1);
    cudaGetSymbolAddress((void**)&x2, g_xp2);
    cudaGetSymbolAddress((void**)&x3, g_xp3);

    norm_kernel<<<(B_ * L_) / 8, 256>>>(graph, rn);
    // EW = E @ Wx (256x256x256)
    gemm_nn<<<dim3(2, 2), 256>>>(E, Wx, ew, 256, nullptr);
    // t = (seq @ EW) * rnorm   (M=8192, K=256, N=256)
    gemm_nn<<<dim3(2, 64), 256>>>(seq, ew, tt, 256, rn);
    // xproj partials: grid (2, 8, 32), z = b*4 + ks, each K quarter = 256
    gemm_tn<<<dim3(2, 8, 32), 256>>>(graph, tt, x0, x1, x2, x3);
    // scan (adds the four x partials on the fly)
    cudaFuncSetAttribute(scan_kernel, cudaFuncAttributeMaxDynamicSharedMemorySize,
                         SCAN_SMEM_BYTES);
    scan_kernel<<<B_, 256, SCAN_SMEM_BYTES>>>(Wh, x0, x1, x2, x3, bias, out);
}

// round 8
// speedup vs baseline: 1.0809x; 1.0809x over previous
#include <cuda_runtime.h>
#include <math.h>

#define B_ 8
#define L_ 1024
#define D_ 256
#define U_ 256
#define NCHUNK 8
#define CHUNK 128

typedef unsigned long long ull;

// ---------------- scratch (device globals; no allocation allowed) ----------
__device__ float g_EW[D_ * U_];          // E @ Wx            (256 KB)
__device__ float g_rnorm[B_ * L_];       // 1/max(rowsum,eps) (32 KB)
__device__ float g_t[B_ * L_ * U_];      // (seq@EW)*rnorm    (8 MB)
__device__ float g_xp0[B_ * L_ * U_];    // G^T @ t partials  (8 MB each)
__device__ float g_xp1[B_ * L_ * U_];
__device__ float g_xp2[B_ * L_ * U_];
__device__ float g_xp3[B_ * L_ * U_];
__device__ int g_flags[B_][NCHUNK];      // producer->consumer chunk flags

// ---------------- packed f32x2 helpers (sm_103a) ----------------------------
__device__ __forceinline__ ull pk2(float lo, float hi) {
    ull r; asm("mov.b64 %0,{%1,%2};" : "=l"(r) : "f"(lo), "f"(hi)); return r;
}
__device__ __forceinline__ void ffma2(ull& d, ull a, ull b) {
    asm("fma.rn.f32x2 %0,%1,%2,%0;" : "+l"(d) : "l"(a), "l"(b));
}
__device__ __forceinline__ float2 up2(ull a) {
    float lo, hi; asm("mov.b64 {%0,%1},%2;" : "=f"(lo), "=f"(hi) : "l"(a));
    float2 r; r.x = lo; r.y = hi; return r;
}
// tanh(z) = 1 - 2/(1+exp(2z)) via MUFU (rel err ~1e-6; validated R3-R7)
__device__ __forceinline__ float fast_tanh(float z) {
    float t2 = z * 2.885390081777927f;  // 2*log2(e)
    float ex; asm("ex2.approx.f32 %0,%1;" : "=f"(ex) : "f"(t2));
    float den = ex + 1.0f;
    float rc; asm("rcp.approx.f32 %0,%1;" : "=f"(rc) : "f"(den));
    return fmaf(-2.0f, rc, 1.0f);
}

// ---------------- 0) zero chunk flags (graph-replay safe) -------------------
__global__ void zero_flags_kernel() {
    int i = threadIdx.x;
    if (i < B_ * NCHUNK) ((int*)g_flags)[i] = 0;
}

// ---------------- 1) rnorm[b,l] = 1 / max(sum_m graph[b,l,m], 1e-7) ---------
__global__ __launch_bounds__(256) void norm_kernel(const float* __restrict__ graph,
                                                   float* __restrict__ rnorm) {
    int warp = (blockIdx.x * blockDim.x + threadIdx.x) >> 5;
    int lane = threadIdx.x & 31;
    if (warp >= B_ * L_) return;
    const float4* row = (const float4*)(graph + (size_t)warp * L_);
    float s = 0.f;
#pragma unroll
    for (int i = lane; i < L_ / 4; i += 32) {
        float4 v = row[i];
        s += (v.x + v.y) + (v.z + v.w);
    }
#pragma unroll
    for (int o = 16; o; o >>= 1) s += __shfl_xor_sync(0xffffffffu, s, o);
    if (lane == 0) rnorm[warp] = 1.f / fmaxf(s, 1e-7f);
}

// ---------------- 2) GEMM NN (proven R2 version): 128x128 tile, BK=16 -------
__global__ __launch_bounds__(256) void gemm_nn(const float* __restrict__ A,
                                               const float* __restrict__ Bm,
                                               float* __restrict__ C, int K,
                                               const float* __restrict__ rowscale) {
    __shared__ float As[2][16][128];
    __shared__ float Bs[2][16][128];
    const int N = 256;
    const int m0 = blockIdx.y * 128, n0 = blockIdx.x * 128;
    const int t = threadIdx.x;
    const int tx = t & 15, ty = t >> 4;

    ull acc[8][4];
#pragma unroll
    for (int i = 0; i < 8; i++)
#pragma unroll
        for (int j = 0; j < 4; j++) acc[i][j] = 0ull;

    int am[2], akg[2], bkk[2], bng[2];
#pragma unroll
    for (int i = 0; i < 2; i++) {
        int f4 = t + i * 256;
        am[i] = f4 >> 2; akg[i] = f4 & 3;
        bkk[i] = f4 >> 5; bng[i] = f4 & 31;
    }

    float4 ra[2], rb[2];
#pragma unroll
    for (int i = 0; i < 2; i++) {
        ra[i] = *(const float4*)(A + (size_t)(m0 + am[i]) * K + akg[i] * 4);
        rb[i] = *(const float4*)(Bm + (size_t)bkk[i] * N + n0 + bng[i] * 4);
    }

    int cur = 0;
    for (int k0 = 0; k0 < K; k0 += 16) {
#pragma unroll
        for (int i = 0; i < 2; i++) {
            As[cur][akg[i] * 4 + 0][am[i]] = ra[i].x;
            As[cur][akg[i] * 4 + 1][am[i]] = ra[i].y;
            As[cur][akg[i] * 4 + 2][am[i]] = ra[i].z;
            As[cur][akg[i] * 4 + 3][am[i]] = ra[i].w;
            *(float4*)&Bs[cur][bkk[i]][bng[i] * 4] = rb[i];
        }
        __syncthreads();
        if (k0 + 16 < K) {
#pragma unroll
            for (int i = 0; i < 2; i++) {
                ra[i] = *(const float4*)(A + (size_t)(m0 + am[i]) * K + k0 + 16 + akg[i] * 4);
                rb[i] = *(const float4*)(Bm + (size_t)(k0 + 16 + bkk[i]) * N + n0 + bng[i] * 4);
            }
        }
#pragma unroll
        for (int kk = 0; kk < 16; kk++) {
            float4 a0 = *(float4*)&As[cur][kk][ty * 8];
            float4 a1 = *(float4*)&As[cur][kk][ty * 8 + 4];
            float4 b0 = *(float4*)&Bs[cur][kk][tx * 8];
            float4 b1 = *(float4*)&Bs[cur][kk][tx * 8 + 4];
            ull bp0 = pk2(b0.x, b0.y), bp1 = pk2(b0.z, b0.w);
            ull bp2 = pk2(b1.x, b1.y), bp3 = pk2(b1.z, b1.w);
            float av[8] = {a0.x, a0.y, a0.z, a0.w, a1.x, a1.y, a1.z, a1.w};
#pragma unroll
            for (int i = 0; i < 8; i++) {
                ull ad = pk2(av[i], av[i]);
                ffma2(acc[i][0], ad, bp0);
                ffma2(acc[i][1], ad, bp1);
                ffma2(acc[i][2], ad, bp2);
                ffma2(acc[i][3], ad, bp3);
            }
        }
        cur ^= 1;
    }
#pragma unroll
    for (int i = 0; i < 8; i++) {
        int row = m0 + ty * 8 + i;
        float sc = rowscale ? rowscale[row] : 1.f;
        float2 v0 = up2(acc[i][0]), v1 = up2(acc[i][1]);
        float2 v2 = up2(acc[i][2]), v3 = up2(acc[i][3]);
        float4 o0 = make_float4(v0.x * sc, v0.y * sc, v1.x * sc, v1.y * sc);
        float4 o1 = make_float4(v2.x * sc, v2.y * sc, v3.x * sc, v3.y * sc);
        *(float4*)(C + (size_t)row * N + n0 + tx * 8) = o0;
        *(float4*)(C + (size_t)row * N + n0 + tx * 8 + 4) = o1;
    }
}

// ---------------- fused kernel: scan CTAs (0..7) + gemm_tn CTAs (8..519) ----
// gemm CTA gid = bid-8: nt = gid&1, bks = (gid>>1)&31 (b*4+ks), mchunk = gid>>6.
// mchunk varies slowest so all batches' chunk 0 is produced first.
// Scan CTA b waits on g_flags[b][c] == 8 (2 ntiles x 4 ks) per 128-step chunk.
#define RF_PAIRS 26
#define SM_PAIRS 6
#define WS_ULLS (SM_PAIRS * 4 * 4 * 64)          // 6144 ull = 48 KB
#define SCAN_SMEM_BYTES (WS_ULLS * 8 + 4 * 256 * 4 + 2 * 256 * 4)

__global__ __launch_bounds__(256) void fused_kernel(
    const float* __restrict__ graph, const float* __restrict__ tmat,
    const float* __restrict__ Wh, const float* __restrict__ bias,
    float* __restrict__ xq0, float* __restrict__ xq1,
    float* __restrict__ xq2, float* __restrict__ xq3,
    float* __restrict__ out) {
    extern __shared__ unsigned char smraw[];
    const int tid = threadIdx.x;

    if (blockIdx.x >= 8) {
        // ================= gemm_tn path (K-split 4) =========================
        float (*As)[16][128] = (float (*)[16][128])smraw;
        float (*Bs)[16][128] = (float (*)[16][128])(smraw + 2 * 16 * 128 * 4);
        const int gid = blockIdx.x - 8;
        const int nt = gid & 1, bks = (gid >> 1) & 31, mchunk = gid >> 6;
        const int b = bks >> 2, ks = bks & 3;
        const int kbeg = ks * (L_ / 4), kend = kbeg + (L_ / 4);
        const int N = 256, lda = L_;
        const float* Ab = graph + (size_t)b * L_ * L_;
        const float* Bb = tmat + (size_t)b * L_ * U_;
        float* Cs = (ks == 0) ? xq0 : (ks == 1) ? xq1 : (ks == 2) ? xq2 : xq3;
        float* C = Cs + (size_t)b * L_ * U_;
        const int m0 = mchunk * 128, n0 = nt * 128;
        const int tx = tid & 15, ty = tid >> 4;

        ull acc[8][4];
#pragma unroll
        for (int i = 0; i < 8; i++)
#pragma unroll
            for (int j = 0; j < 4; j++) acc[i][j] = 0ull;

        int kk_[2], g_[2];
#pragma unroll
        for (int i = 0; i < 2; i++) {
            int f4 = tid + i * 256;
            kk_[i] = f4 >> 5; g_[i] = f4 & 31;
        }

        float4 ra[2], rb[2];
#pragma unroll
        for (int i = 0; i < 2; i++) {
            ra[i] = *(const float4*)(Ab + (size_t)(kbeg + kk_[i]) * lda + m0 + g_[i] * 4);
            rb[i] = *(const float4*)(Bb + (size_t)(kbeg + kk_[i]) * N + n0 + g_[i] * 4);
        }

        int cur = 0;
        for (int k0 = kbeg; k0 < kend; k0 += 16) {
#pragma unroll
            for (int i = 0; i < 2; i++) {
                *(float4*)&As[cur][kk_[i]][g_[i] * 4] = ra[i];
                *(float4*)&Bs[cur][kk_[i]][g_[i] * 4] = rb[i];
            }
            __syncthreads();
            if (k0 + 16 < kend) {
#pragma unroll
                for (int i = 0; i < 2; i++) {
                    ra[i] = *(const float4*)(Ab + (size_t)(k0 + 16 + kk_[i]) * lda + m0 + g_[i] * 4);
                    rb[i] = *(const float4*)(Bb + (size_t)(k0 + 16 + kk_[i]) * N + n0 + g_[i] * 4);
                }
            }
#pragma unroll
            for (int kk = 0; kk < 16; kk++) {
                float4 a0 = *(float4*)&As[cur][kk][ty * 8];
                float4 a1 = *(float4*)&As[cur][kk][ty * 8 + 4];
                float4 b0 = *(float4*)&Bs[cur][kk][tx * 8];
                float4 b1 = *(float4*)&Bs[cur][kk][tx * 8 + 4];
                ull bp0 = pk2(b0.x, b0.y), bp1 = pk2(b0.z, b0.w);
                ull bp2 = pk2(b1.x, b1.y), bp3 = pk2(b1.z, b1.w);
                float av[8] = {a0.x, a0.y, a0.z, a0.w, a1.x, a1.y, a1.z, a1.w};
#pragma unroll
                for (int i = 0; i < 8; i++) {
                    ull ad = pk2(av[i], av[i]);
                    ffma2(acc[i][0], ad, bp0);
                    ffma2(acc[i][1], ad, bp1);
                    ffma2(acc[i][2], ad, bp2);
                    ffma2(acc[i][3], ad, bp3);
                }
            }
            cur ^= 1;
        }
#pragma unroll
        for (int i = 0; i < 8; i++) {
            int row = m0 + ty * 8 + i;
            float2 v0 = up2(acc[i][0]), v1 = up2(acc[i][1]);
            float2 v2 = up2(acc[i][2]), v3 = up2(acc[i][3]);
            float4 o0 = make_float4(v0.x, v0.y, v1.x, v1.y);
            float4 o1 = make_float4(v2.x, v2.y, v3.x, v3.y);
            *(float4*)(C + (size_t)row * N + n0 + tx * 8) = o0;
            *(float4*)(C + (size_t)row * N + n0 + tx * 8 + 4) = o1;
        }
        // publish: all stores visible, then bump the chunk flag
        __threadfence();
        __syncthreads();
        if (tid == 0) atomicAdd(&g_flags[b][mchunk], 1);
        return;
    }

    // ================= scan path (R6 skeleton, chunked waits) ===============
    ull* ws = (ull*)smraw;                                  // 48 KB weights
    float* part = (float*)(smraw + WS_ULLS * 8);            // 4 KB partials
    float* hbuf = part + 4 * 256;                           // 2 KB h (double buf)

    const int b = blockIdx.x;
    const int w = tid >> 5, l = tid & 31;
    const int ks = w >> 1, oh = w & 1;
    const int u0 = oh * 128 + l * 4;

    for (int idx = tid; idx < WS_ULLS; idx += 256) {
        int e = idx >> 6, r = idx & 63;
        int ps = e >> 4, ksf = (e >> 2) & 3, jf = e & 3;
        int ohf = r >> 5, lf = r & 31;
        int uf = ohf * 128 + lf * 4 + jf;
        int kf = ksf * 64 + 2 * (RF_PAIRS + ps);
        ws[idx] = pk2(Wh[kf * U_ + uf], Wh[(kf + 1) * U_ + uf]);
    }

    ull wreg[4][RF_PAIRS];
#pragma unroll
    for (int j = 0; j < 4; j++)
#pragma unroll
        for (int p = 0; p < RF_PAIRS; p++) {
            int k = ks * 64 + 2 * p;
            wreg[j][p] = pk2(Wh[k * U_ + u0 + j], Wh[(k + 1) * U_ + u0 + j]);
        }

    hbuf[tid] = 0.f;
    hbuf[256 + tid] = 0.f;
    const float bv = bias[tid];
    __syncthreads();

    const float* xp0 = xq0 + (size_t)b * L_ * U_ + tid;
    const float* xp1 = xq1 + (size_t)b * L_ * U_ + tid;
    const float* xp2 = xq2 + (size_t)b * L_ * U_ + tid;
    const float* xp3 = xq3 + (size_t)b * L_ * U_ + tid;
    float* op = out + (size_t)b * L_ * U_ + tid;
    int cur = 0;

    const ull* wsp = ws + ks * 256 + oh * 32 + l;
    volatile int* flagp = &g_flags[b][0];

    for (int c = 0; c < NCHUNK; c++) {
        if (tid == 0) {
            while (flagp[c] < 8) { }
        }
        __syncthreads();
        __threadfence();  // acquire: pair with producers' release fences

        for (int si = 0; si < CHUNK; si++) {
            int s = c * CHUNK + si;
            // load this step's x at the top; consumed ~1000 cy later
            size_t xo = (size_t)s * U_;
            float xa = xp0[xo], xb = xp1[xo], xc = xp2[xo], xd = xp3[xo];

            const ulonglong2* hp2 = (const ulonglong2*)(hbuf + cur * 256 + ks * 64);
            ull a0 = 0ull, a1 = 0ull, a2 = 0ull, a3 = 0ull;
#pragma unroll
            for (int q = 0; q < 13; q++) {   // pairs 0..25 (RF)
                ulonglong2 hv = hp2[q];
                ffma2(a0, hv.x, wreg[0][2 * q]);
                ffma2(a1, hv.x, wreg[1][2 * q]);
                ffma2(a2, hv.x, wreg[2][2 * q]);
                ffma2(a3, hv.x, wreg[3][2 * q]);
                ffma2(a0, hv.y, wreg[0][2 * q + 1]);
                ffma2(a1, hv.y, wreg[1][2 * q + 1]);
                ffma2(a2, hv.y, wreg[2][2 * q + 1]);
                ffma2(a3, hv.y, wreg[3][2 * q + 1]);
            }
#pragma unroll
            for (int qq = 0; qq < 3; qq++) { // pairs 26..31 (SMEM)
                ulonglong2 hv = hp2[13 + qq];
                int ps0 = 2 * qq, ps1 = 2 * qq + 1;
                ffma2(a0, hv.x, wsp[ps0 * 1024 + 0 * 64]);
                ffma2(a1, hv.x, wsp[ps0 * 1024 + 1 * 64]);
                ffma2(a2, hv.x, wsp[ps0 * 1024 + 2 * 64]);
                ffma2(a3, hv.x, wsp[ps0 * 1024 + 3 * 64]);
                ffma2(a0, hv.y, wsp[ps1 * 1024 + 0 * 64]);
                ffma2(a1, hv.y, wsp[ps1 * 1024 + 1 * 64]);
                ffma2(a2, hv.y, wsp[ps1 * 1024 + 2 * 64]);
                ffma2(a3, hv.y, wsp[ps1 * 1024 + 3 * 64]);
            }
            float2 v0 = up2(a0), v1 = up2(a1), v2 = up2(a2), v3 = up2(a3);
            float4 pr = make_float4(v0.x + v0.y, v1.x + v1.y,
                                    v2.x + v2.y, v3.x + v3.y);
            *(float4*)&part[ks * 256 + u0] = pr;
            __syncthreads();

            float xv = (xa + xb) + (xc + xd);
            float z = part[tid] + part[256 + tid] + part[512 + tid] +
                      part[768 + tid] + xv + bv;
            float h = fast_tanh(z);
            hbuf[(cur ^ 1) * 256 + tid] = h;
            op[xo] = h;
            cur ^= 1;
            __syncthreads();
        }
    }
}

// ---------------- launch --------------------------------------------------
extern "C" void kernel_launch(void* const* d_in, const int* in_sizes, int n_in,
                              void* d_out, int out_size) {
    const float* seq = (const float*)d_in[0];    // (8,1024,256)
    const float* graph = (const float*)d_in[1];  // (8,1024,1024)
    const float* E = (const float*)d_in[2];      // (256,256)
    const float* Wx = (const float*)d_in[3];     // (256,256)
    const float* Wh = (const float*)d_in[4];     // (256,256)
    const float* bias = (const float*)d_in[5];   // (256,)
    float* out = (float*)d_out;                  // (8,1024,256)

    float *ew, *rn, *tt, *x0, *x1, *x2, *x3;
    cudaGetSymbolAddress((void**)&ew, g_EW);
    cudaGetSymbolAddress((void**)&rn, g_rnorm);
    cudaGetSymbolAddress((void**)&tt, g_t);
    cudaGetSymbolAddress((void**)&x0, g_xp0);
    cudaGetSymbolAddress((void**)&x1, g_xp1);
    cudaGetSymbolAddress((void**)&x2, g_xp2);
    cudaGetSymbolAddress((void**)&x3, g_xp3);

    zero_flags_kernel<<<1, 64>>>();
    norm_kernel<<<(B_ * L_) / 8, 256>>>(graph, rn);
    // EW = E @ Wx (256x256x256)
    gemm_nn<<<dim3(2, 2), 256>>>(E, Wx, ew, 256, nullptr);
    // t = (seq @ EW) * rnorm   (M=8192, K=256, N=256)
    gemm_nn<<<dim3(2, 64), 256>>>(seq, ew, tt, 256, rn);
    // fused: 8 scan CTAs + 512 gemm_tn CTAs (producer-consumer via flags)
    cudaFuncSetAttribute(fused_kernel, cudaFuncAttributeMaxDynamicSharedMemorySize,
                         SCAN_SMEM_BYTES);
    fused_kernel<<<8 + 512, 256, SCAN_SMEM_BYTES>>>(graph, tt, Wh, bias,
                                                    x0, x1, x2, x3, out);
}

// round 9
// speedup vs baseline: 1.1194x; 1.0357x over previous
#include <cuda_runtime.h>
#include <math.h>

#define B_ 8
#define L_ 1024
#define D_ 256
#define U_ 256
#define NCHUNK 8
#define CHUNK 128

typedef unsigned long long ull;

// ---------------- scratch (device globals; no allocation allowed) ----------
__device__ float g_EW[D_ * U_];          // E @ Wx            (256 KB)
__device__ float g_rnorm[B_ * L_];       // 1/max(rowsum,eps) (32 KB)
__device__ float g_tp0[B_ * L_ * U_];    // (seq[:,0:128]@EW[0:128])*rnorm
__device__ float g_tp1[B_ * L_ * U_];    // (seq[:,128:256]@EW[128:256])*rnorm
__device__ float g_xp0[B_ * L_ * U_];    // G^T @ t partials  (8 MB each)
__device__ float g_xp1[B_ * L_ * U_];
__device__ float g_xp2[B_ * L_ * U_];
__device__ float g_xp3[B_ * L_ * U_];
__device__ int g_flags[B_][NCHUNK];      // producer->consumer chunk flags

// ---------------- packed f32x2 helpers (sm_103a) ----------------------------
__device__ __forceinline__ ull pk2(float lo, float hi) {
    ull r; asm("mov.b64 %0,{%1,%2};" : "=l"(r) : "f"(lo), "f"(hi)); return r;
}
__device__ __forceinline__ void ffma2(ull& d, ull a, ull b) {
    asm("fma.rn.f32x2 %0,%1,%2,%0;" : "+l"(d) : "l"(a), "l"(b));
}
__device__ __forceinline__ float2 up2(ull a) {
    float lo, hi; asm("mov.b64 {%0,%1},%2;" : "=f"(lo), "=f"(hi) : "l"(a));
    float2 r; r.x = lo; r.y = hi; return r;
}
// tanh(z) = 1 - 2/(1+exp(2z)) via MUFU (rel err ~1e-6; validated R3-R8)
__device__ __forceinline__ float fast_tanh(float z) {
    float t2 = z * 2.885390081777927f;  // 2*log2(e)
    float ex; asm("ex2.approx.f32 %0,%1;" : "=f"(ex) : "f"(t2));
    float den = ex + 1.0f;
    float rc; asm("rcp.approx.f32 %0,%1;" : "=f"(rc) : "f"(den));
    return fmaf(-2.0f, rc, 1.0f);
}

// ---------------- 0) zero chunk flags (graph-replay safe) -------------------
__global__ void zero_flags_kernel() {
    int i = threadIdx.x;
    if (i < B_ * NCHUNK) ((int*)g_flags)[i] = 0;
}

// ---------------- 1) rnorm[b,l] = 1 / max(sum_m graph[b,l,m], 1e-7) ---------
__global__ __launch_bounds__(256) void norm_kernel(const float* __restrict__ graph,
                                                   float* __restrict__ rnorm) {
    int warp = (blockIdx.x * blockDim.x + threadIdx.x) >> 5;
    int lane = threadIdx.x & 31;
    if (warp >= B_ * L_) return;
    const float4* row = (const float4*)(graph + (size_t)warp * L_);
    float s = 0.f;
#pragma unroll
    for (int i = lane; i < L_ / 4; i += 32) {
        float4 v = row[i];
        s += (v.x + v.y) + (v.z + v.w);
    }
#pragma unroll
    for (int o = 16; o; o >>= 1) s += __shfl_xor_sync(0xffffffffu, s, o);
    if (lane == 0) rnorm[warp] = 1.f / fmaxf(s, 1e-7f);
}

// ---------------- 2) GEMM NN: 128x128 tile, BK=16, optional K-split --------
// blockIdx.z selects K half [z*Ksub, (z+1)*Ksub) and output buffer C0/C1.
__global__ __launch_bounds__(256) void gemm_nn(const float* __restrict__ A,
                                               const float* __restrict__ Bm,
                                               float* __restrict__ C0,
                                               float* __restrict__ C1,
                                               int K, int Ksub,
                                               const float* __restrict__ rowscale) {
    __shared__ float As[2][16][128];
    __shared__ float Bs[2][16][128];
    const int N = 256;
    const int m0 = blockIdx.y * 128, n0 = blockIdx.x * 128;
    const int kz = blockIdx.z;
    const int kbeg = kz * Ksub, kend = kbeg + Ksub;
    float* C = kz ? C1 : C0;
    const int t = threadIdx.x;
    const int tx = t & 15, ty = t >> 4;

    ull acc[8][4];
#pragma unroll
    for (int i = 0; i < 8; i++)
#pragma unroll
        for (int j = 0; j < 4; j++) acc[i][j] = 0ull;

    int am[2], akg[2], bkk[2], bng[2];
#pragma unroll
    for (int i = 0; i < 2; i++) {
        int f4 = t + i * 256;
        am[i] = f4 >> 2; akg[i] = f4 & 3;
        bkk[i] = f4 >> 5; bng[i] = f4 & 31;
    }

    float4 ra[2], rb[2];
#pragma unroll
    for (int i = 0; i < 2; i++) {
        ra[i] = *(const float4*)(A + (size_t)(m0 + am[i]) * K + kbeg + akg[i] * 4);
        rb[i] = *(const float4*)(Bm + (size_t)(kbeg + bkk[i]) * N + n0 + bng[i] * 4);
    }

    int cur = 0;
    for (int k0 = kbeg; k0 < kend; k0 += 16) {
#pragma unroll
        for (int i = 0; i < 2; i++) {
            As[cur][akg[i] * 4 + 0][am[i]] = ra[i].x;
            As[cur][akg[i] * 4 + 1][am[i]] = ra[i].y;
            As[cur][akg[i] * 4 + 2][am[i]] = ra[i].z;
            As[cur][akg[i] * 4 + 3][am[i]] = ra[i].w;
            *(float4*)&Bs[cur][bkk[i]][bng[i] * 4] = rb[i];
        }
        __syncthreads();
        if (k0 + 16 < kend) {
#pragma unroll
            for (int i = 0; i < 2; i++) {
                ra[i] = *(const float4*)(A + (size_t)(m0 + am[i]) * K + k0 + 16 + akg[i] * 4);
                rb[i] = *(const float4*)(Bm + (size_t)(k0 + 16 + bkk[i]) * N + n0 + bng[i] * 4);
            }
        }
#pragma unroll
        for (int kk = 0; kk < 16; kk++) {
            float4 a0 = *(float4*)&As[cur][kk][ty * 8];
            float4 a1 = *(float4*)&As[cur][kk][ty * 8 + 4];
            float4 b0 = *(float4*)&Bs[cur][kk][tx * 8];
            float4 b1 = *(float4*)&Bs[cur][kk][tx * 8 + 4];
            ull bp0 = pk2(b0.x, b0.y), bp1 = pk2(b0.z, b0.w);
            ull bp2 = pk2(b1.x, b1.y), bp3 = pk2(b1.z, b1.w);
            float av[8] = {a0.x, a0.y, a0.z, a0.w, a1.x, a1.y, a1.z, a1.w};
#pragma unroll
            for (int i = 0; i < 8; i++) {
                ull ad = pk2(av[i], av[i]);
                ffma2(acc[i][0], ad, bp0);
                ffma2(acc[i][1], ad, bp1);
                ffma2(acc[i][2], ad, bp2);
                ffma2(acc[i][3], ad, bp3);
            }
        }
        cur ^= 1;
    }
#pragma unroll
    for (int i = 0; i < 8; i++) {
        int row = m0 + ty * 8 + i;
        float sc = rowscale ? rowscale[row] : 1.f;
        float2 v0 = up2(acc[i][0]), v1 = up2(acc[i][1]);
        float2 v2 = up2(acc[i][2]), v3 = up2(acc[i][3]);
        float4 o0 = make_float4(v0.x * sc, v0.y * sc, v1.x * sc, v1.y * sc);
        float4 o1 = make_float4(v2.x * sc, v2.y * sc, v3.x * sc, v3.y * sc);
        *(float4*)(C + (size_t)row * N + n0 + tx * 8) = o0;
        *(float4*)(C + (size_t)row * N + n0 + tx * 8 + 4) = o1;
    }
}

// ---------------- fused kernel: scan CTAs (0..7) + gemm_tn CTAs (8..519) ----
// gemm B-tile is tp0+tp1 summed at fill (t K-split partials).
#define RF_PAIRS 26
#define SM_PAIRS 6
#define WS_ULLS (SM_PAIRS * 4 * 4 * 64)          // 6144 ull = 48 KB
#define SCAN_SMEM_BYTES (WS_ULLS * 8 + 4 * 256 * 4 + 2 * 256 * 4)

__global__ __launch_bounds__(256) void fused_kernel(
    const float* __restrict__ graph,
    const float* __restrict__ tp0, const float* __restrict__ tp1,
    const float* __restrict__ Wh, const float* __restrict__ bias,
    float* __restrict__ xq0, float* __restrict__ xq1,
    float* __restrict__ xq2, float* __restrict__ xq3,
    float* __restrict__ out) {
    extern __shared__ unsigned char smraw[];
    const int tid = threadIdx.x;

    if (blockIdx.x >= 8) {
        // ================= gemm_tn path (K-split 4) =========================
        float (*As)[16][128] = (float (*)[16][128])smraw;
        float (*Bs)[16][128] = (float (*)[16][128])(smraw + 2 * 16 * 128 * 4);
        const int gid = blockIdx.x - 8;
        const int nt = gid & 1, bks = (gid >> 1) & 31, mchunk = gid >> 6;
        const int b = bks >> 2, ks = bks & 3;
        const int kbeg = ks * (L_ / 4), kend = kbeg + (L_ / 4);
        const int N = 256, lda = L_;
        const float* Ab = graph + (size_t)b * L_ * L_;
        const float* Bb0 = tp0 + (size_t)b * L_ * U_;
        const float* Bb1 = tp1 + (size_t)b * L_ * U_;
        float* Cs = (ks == 0) ? xq0 : (ks == 1) ? xq1 : (ks == 2) ? xq2 : xq3;
        float* C = Cs + (size_t)b * L_ * U_;
        const int m0 = mchunk * 128, n0 = nt * 128;
        const int tx = tid & 15, ty = tid >> 4;

        ull acc[8][4];
#pragma unroll
        for (int i = 0; i < 8; i++)
#pragma unroll
            for (int j = 0; j < 4; j++) acc[i][j] = 0ull;

        int kk_[2], g_[2];
#pragma unroll
        for (int i = 0; i < 2; i++) {
            int f4 = tid + i * 256;
            kk_[i] = f4 >> 5; g_[i] = f4 & 31;
        }

        float4 ra[2], rb0[2], rb1[2];
#pragma unroll
        for (int i = 0; i < 2; i++) {
            size_t ko = (size_t)(kbeg + kk_[i]);
            ra[i] = *(const float4*)(Ab + ko * lda + m0 + g_[i] * 4);
            rb0[i] = *(const float4*)(Bb0 + ko * N + n0 + g_[i] * 4);
            rb1[i] = *(const float4*)(Bb1 + ko * N + n0 + g_[i] * 4);
        }

        int cur = 0;
        for (int k0 = kbeg; k0 < kend; k0 += 16) {
#pragma unroll
            for (int i = 0; i < 2; i++) {
                *(float4*)&As[cur][kk_[i]][g_[i] * 4] = ra[i];
                float4 s = make_float4(rb0[i].x + rb1[i].x, rb0[i].y + rb1[i].y,
                                       rb0[i].z + rb1[i].z, rb0[i].w + rb1[i].w);
                *(float4*)&Bs[cur][kk_[i]][g_[i] * 4] = s;
            }
            __syncthreads();
            if (k0 + 16 < kend) {
#pragma unroll
                for (int i = 0; i < 2; i++) {
                    size_t ko = (size_t)(k0 + 16 + kk_[i]);
                    ra[i] = *(const float4*)(Ab + ko * lda + m0 + g_[i] * 4);
                    rb0[i] = *(const float4*)(Bb0 + ko * N + n0 + g_[i] * 4);
                    rb1[i] = *(const float4*)(Bb1 + ko * N + n0 + g_[i] * 4);
                }
            }
#pragma unroll
            for (int kk = 0; kk < 16; kk++) {
                float4 a0 = *(float4*)&As[cur][kk][ty * 8];
                float4 a1 = *(float4*)&As[cur][kk][ty * 8 + 4];
                float4 b0 = *(float4*)&Bs[cur][kk][tx * 8];
                float4 b1 = *(float4*)&Bs[cur][kk][tx * 8 + 4];
                ull bp0 = pk2(b0.x, b0.y), bp1 = pk2(b0.z, b0.w);
                ull bp2 = pk2(b1.x, b1.y), bp3 = pk2(b1.z, b1.w);
                float av[8] = {a0.x, a0.y, a0.z, a0.w, a1.x, a1.y, a1.z, a1.w};
#pragma unroll
                for (int i = 0; i < 8; i++) {
                    ull ad = pk2(av[i], av[i]);
                    ffma2(acc[i][0], ad, bp0);
                    ffma2(acc[i][1], ad, bp1);
                    ffma2(acc[i][2], ad, bp2);
                    ffma2(acc[i][3], ad, bp3);
                }
            }
            cur ^= 1;
        }
#pragma unroll
        for (int i = 0; i < 8; i++) {
            int row = m0 + ty * 8 + i;
            float2 v0 = up2(acc[i][0]), v1 = up2(acc[i][1]);
            float2 v2 = up2(acc[i][2]), v3 = up2(acc[i][3]);
            float4 o0 = make_float4(v0.x, v0.y, v1.x, v1.y);
            float4 o1 = make_float4(v2.x, v2.y, v3.x, v3.y);
            *(float4*)(C + (size_t)row * N + n0 + tx * 8) = o0;
            *(float4*)(C + (size_t)row * N + n0 + tx * 8 + 4) = o1;
        }
        __threadfence();
        __syncthreads();
        if (tid == 0) atomicAdd(&g_flags[b][mchunk], 1);
        return;
    }

    // ================= scan path (SMEM-weight FMAs FIRST) ===================
    ull* ws = (ull*)smraw;                                  // 48 KB weights
    float* part = (float*)(smraw + WS_ULLS * 8);            // 4 KB partials
    float* hbuf = part + 4 * 256;                           // 2 KB h (double buf)

    const int b = blockIdx.x;
    const int w = tid >> 5, l = tid & 31;
    const int ks = w >> 1, oh = w & 1;
    const int u0 = oh * 128 + l * 4;

    for (int idx = tid; idx < WS_ULLS; idx += 256) {
        int e = idx >> 6, r = idx & 63;
        int ps = e >> 4, ksf = (e >> 2) & 3, jf = e & 3;
        int ohf = r >> 5, lf = r & 31;
        int uf = ohf * 128 + lf * 4 + jf;
        int kf = ksf * 64 + 2 * (RF_PAIRS + ps);
        ws[idx] = pk2(Wh[kf * U_ + uf], Wh[(kf + 1) * U_ + uf]);
    }

    ull wreg[4][RF_PAIRS];
#pragma unroll
    for (int j = 0; j < 4; j++)
#pragma unroll
        for (int p = 0; p < RF_PAIRS; p++) {
            int k = ks * 64 + 2 * p;
            wreg[j][p] = pk2(Wh[k * U_ + u0 + j], Wh[(k + 1) * U_ + u0 + j]);
        }

    hbuf[tid] = 0.f;
    hbuf[256 + tid] = 0.f;
    const float bv = bias[tid];
    __syncthreads();

    const float* xp0 = xq0 + (size_t)b * L_ * U_ + tid;
    const float* xp1 = xq1 + (size_t)b * L_ * U_ + tid;
    const float* xp2 = xq2 + (size_t)b * L_ * U_ + tid;
    const float* xp3 = xq3 + (size_t)b * L_ * U_ + tid;
    float* op = out + (size_t)b * L_ * U_ + tid;
    int cur = 0;

    const ull* wsp = ws + ks * 256 + oh * 32 + l;
    volatile int* flagp = &g_flags[b][0];

    for (int c = 0; c < NCHUNK; c++) {
        if (tid == 0) {
            while (flagp[c] < 8) { }
        }
        __syncthreads();
        __threadfence();  // acquire: pair with producers' release fences

        for (int si = 0; si < CHUNK; si++) {
            int s = c * CHUNK + si;
            size_t xo = (size_t)s * U_;
            float xa = xp0[xo], xb = xp1[xo], xc = xp2[xo], xd = xp3[xo];

            const ulonglong2* hp2 = (const ulonglong2*)(hbuf + cur * 256 + ks * 64);
            ull a0 = 0ull, a1 = 0ull, a2 = 0ull, a3 = 0ull;
            // SMEM-weight FMAs FIRST: LDS issues at the top of the step,
            // its latency overlaps the long RF FMA stream that follows.
#pragma unroll
            for (int qq = 0; qq < 3; qq++) { // pairs 26..31 (SMEM)
                ulonglong2 hv = hp2[13 + qq];
                int ps0 = 2 * qq, ps1 = 2 * qq + 1;
                ffma2(a0, hv.x, wsp[ps0 * 1024 + 0 * 64]);
                ffma2(a1, hv.x, wsp[ps0 * 1024 + 1 * 64]);
                ffma2(a2, hv.x, wsp[ps0 * 1024 + 2 * 64]);
                ffma2(a3, hv.x, wsp[ps0 * 1024 + 3 * 64]);
                ffma2(a0, hv.y, wsp[ps1 * 1024 + 0 * 64]);
                ffma2(a1, hv.y, wsp[ps1 * 1024 + 1 * 64]);
                ffma2(a2, hv.y, wsp[ps1 * 1024 + 2 * 64]);
                ffma2(a3, hv.y, wsp[ps1 * 1024 + 3 * 64]);
            }
#pragma unroll
            for (int q = 0; q < 13; q++) {   // pairs 0..25 (RF)
                ulonglong2 hv = hp2[q];
                ffma2(a0, hv.x, wreg[0][2 * q]);
                ffma2(a1, hv.x, wreg[1][2 * q]);
                ffma2(a2, hv.x, wreg[2][2 * q]);
                ffma2(a3, hv.x, wreg[3][2 * q]);
                ffma2(a0, hv.y, wreg[0][2 * q + 1]);
                ffma2(a1, hv.y, wreg[1][2 * q + 1]);
                ffma2(a2, hv.y, wreg[2][2 * q + 1]);
                ffma2(a3, hv.y, wreg[3][2 * q + 1]);
            }
            float2 v0 = up2(a0), v1 = up2(a1), v2 = up2(a2), v3 = up2(a3);
            float4 pr = make_float4(v0.x + v0.y, v1.x + v1.y,
                                    v2.x + v2.y, v3.x + v3.y);
            float xv = (xa + xb) + (xc + xd);
            *(float4*)&part[ks * 256 + u0] = pr;
            __syncthreads();

            float z = part[tid] + part[256 + tid] + part[512 + tid] +
                      part[768 + tid] + xv + bv;
            float h = fast_tanh(z);
            hbuf[(cur ^ 1) * 256 + tid] = h;
            op[xo] = h;
            cur ^= 1;
            __syncthreads();
        }
    }
}

// ---------------- launch --------------------------------------------------
extern "C" void kernel_launch(void* const* d_in, const int* in_sizes, int n_in,
                              void* d_out, int out_size) {
    const float* seq = (const float*)d_in[0];    // (8,1024,256)
    const float* graph = (const float*)d_in[1];  // (8,1024,1024)
    const float* E = (const float*)d_in[2];      // (256,256)
    const float* Wx = (const float*)d_in[3];     // (256,256)
    const float* Wh = (const float*)d_in[4];     // (256,256)
    const float* bias = (const float*)d_in[5];   // (256,)
    float* out = (float*)d_out;                  // (8,1024,256)

    float *ew, *rn, *t0, *t1, *x0, *x1, *x2, *x3;
    cudaGetSymbolAddress((void**)&ew, g_EW);
    cudaGetSymbolAddress((void**)&rn, g_rnorm);
    cudaGetSymbolAddress((void**)&t0, g_tp0);
    cudaGetSymbolAddress((void**)&t1, g_tp1);
    cudaGetSymbolAddress((void**)&x0, g_xp0);
    cudaGetSymbolAddress((void**)&x1, g_xp1);
    cudaGetSymbolAddress((void**)&x2, g_xp2);
    cudaGetSymbolAddress((void**)&x3, g_xp3);

    zero_flags_kernel<<<1, 64>>>();
    norm_kernel<<<(B_ * L_) / 8, 256>>>(graph, rn);
    // EW = E @ Wx (256x256x256, no K-split: Ksub = 256)
    gemm_nn<<<dim3(2, 2, 1), 256>>>(E, Wx, ew, ew, 256, 256, nullptr);
    // t partials: K-split 2 (Ksub = 128), grid z selects half + buffer
    gemm_nn<<<dim3(2, 64, 2), 256>>>(seq, ew, t0, t1, 256, 128, rn);
    // fused: 8 scan CTAs + 512 gemm_tn CTAs (B-tile = tp0 + tp1)
    cudaFuncSetAttribute(fused_kernel, cudaFuncAttributeMaxDynamicSharedMemorySize,
                         SCAN_SMEM_BYTES);
    fused_kernel<<<8 + 512, 256, SCAN_SMEM_BYTES>>>(graph, t0, t1, Wh, bias,
                                                    x0, x1, x2, x3, out);
}